// round 11
// baseline (speedup 1.0000x reference)
#include <cuda_runtime.h>

// (4,4,3,192,192) fp32 -> (4,4,2,192,192): per-patch KDE entropies (R=3, h=0.1).
// R11: 2-patch horizontal coarsening with SINGLE fused pass (no persistent e[]):
// each thread computes the 57 distinct pair-exps of a 3x4 region (covers two
// adjacent 3x3 patches), shuffles the next frame's exp in lockstep, and
// accumulates 4 entropies (marg/joint x left/right) with scalar fp32.
// Lane layout: lane = 4*sub + sf  (sub = patch-pair slot, sf = frame).

#define WW  192
#define HW  (192 * 192)

#define CM     (-1.9537149f)      // log9 + 1.5*ln(2*pi*0.01)  (C=3 marginal)
#define CJ     (-6.1046541f)      // log9 + 3.0*ln(2*pi*0.01)  (C=6 joint)
#define LN2_9  (0.0770163534f)    // ln(2)/9
#define PSC2   (12.0112240f)      // sqrt(100*log2(e)): exp(-50*d2)=ex2(u.u'+nt+nt')

static __device__ __forceinline__ float fast_ex2(float x)
{ float r; asm("ex2.approx.ftz.f32 %0, %1;" : "=f"(r) : "f"(x)); return r; }

static __device__ __forceinline__ float fast_lg2(float x)
{ float r; asm("lg2.approx.f32 %0, %1;" : "=f"(r) : "f"(x)); return r; }

static __device__ __forceinline__ float prod9(const float s[9])
{
    return ((s[0] * s[1]) * (s[2] * s[3])) *
           ((s[4] * s[5]) * (s[6] * s[7])) * s[8];
}

// Border ring zeroing for one patch's two output channels (cold path).
static __device__ __forceinline__ void zero_border(float* ob, int x, int y)
{
    if (y == 0)   { ob[x + 1] = 0.0f;            ob[HW + x + 1] = 0.0f; }
    if (y == 189) { ob[191*WW + x + 1] = 0.0f;   ob[HW + 191*WW + x + 1] = 0.0f; }
    if (x == 0) {
        ob[(y + 1) * WW] = 0.0f;                 ob[HW + (y + 1) * WW] = 0.0f;
        if (y == 0)   { ob[0] = 0.0f;            ob[HW] = 0.0f; }
        if (y == 189) { ob[191*WW] = 0.0f;       ob[HW + 191*WW] = 0.0f; }
    }
    if (x == 189) {
        ob[(y + 1) * WW + 191] = 0.0f;           ob[HW + (y + 1) * WW + 191] = 0.0f;
        if (y == 0)   { ob[191] = 0.0f;          ob[HW + 191] = 0.0f; }
        if (y == 189) { ob[191*WW + 191] = 0.0f; ob[HW + 191*WW + 191] = 0.0f; }
    }
}

__global__ void __launch_bounds__(128)
je11_kernel(const float* __restrict__ in, float* __restrict__ out)
{
    int lane = threadIdx.x & 31;
    int warp = threadIdx.x >> 5;
    int sf   = lane & 3;          // frame handled by this lane
    int sub  = lane >> 2;         // patch-PAIR slot within warp (8 per warp)

    int x0 = blockIdx.x * 64 + warp * 16 + sub * 2;  // left patch col (even)
    int y  = blockIdx.y;                              // patch row 0..189
    int n  = blockIdx.z;

    bool valid = (x0 < 190);      // x0 even => left and right valid together
    int  xc    = valid ? x0 : 188;

    const float* ib = in + ((size_t)(n * 4 + sf) * 3) * HW + y * WW + xc;

    // ---- load 3 rows x 4 cols x 3 chan, pre-scaled; pixel p = r*4+c ----
    float u[12][3];
    #pragma unroll
    for (int c = 0; c < 3; ++c) {
        const float* bc = ib + c * HW;
        #pragma unroll
        for (int r = 0; r < 3; ++r)
            #pragma unroll
            for (int dx = 0; dx < 4; ++dx)
                u[r * 4 + dx][c] = bc[r * WW + dx] * PSC2;
    }

    // per-pixel -0.5*|u|^2
    float nt[12];
    #pragma unroll
    for (int p = 0; p < 12; ++p) {
        float t = u[p][0] * u[p][0];
        t = fmaf(u[p][1], u[p][1], t);
        t = fmaf(u[p][2], u[p][2], t);
        nt[p] = -0.5f * t;
    }

    // Shuffle source: next frame's lane (same patch pair); frame 3 -> itself.
    int src = (sf == 3) ? lane : (lane + 1);

    // ---- single fused pass over the 57 pairs (|col diff| <= 2) ----
    float sL[9], jL[9], sR[9], jR[9];
    #pragma unroll
    for (int q = 0; q < 9; ++q) { sL[q]=1.0f; jL[q]=1.0f; sR[q]=1.0f; jR[q]=1.0f; }

    #pragma unroll
    for (int i = 0; i < 12; ++i) {
        #pragma unroll
        for (int j = i + 1; j < 12; ++j) {
            const int ri = i >> 2, ci = i & 3;
            const int rj = j >> 2, cj = j & 3;
            if (((ci > cj) ? (ci - cj) : (cj - ci)) > 2) continue; // pruned @CT
            float a = fmaf(u[i][0], u[j][0], nt[i]);
            a = fmaf(u[i][1], u[j][1], a);
            a = fmaf(u[i][2], u[j][2], a);
            a = a + nt[j];
            float ee = fast_ex2(a);                        // exp(-50*d2)
            float en = __shfl_sync(0xffffffffu, ee, src);  // lockstep: same pair
            if (ci <= 2 && cj <= 2) {                      // inside LEFT patch
                sL[ri*3+ci] += ee;            sL[rj*3+cj] += ee;
                jL[ri*3+ci] = fmaf(ee, en, jL[ri*3+ci]);
                jL[rj*3+cj] = fmaf(ee, en, jL[rj*3+cj]);
            }
            if (ci >= 1 && cj >= 1) {                      // inside RIGHT patch
                sR[ri*3+ci-1] += ee;          sR[rj*3+cj-1] += ee;
                jR[ri*3+ci-1] = fmaf(ee, en, jR[ri*3+ci-1]);
                jR[rj*3+cj-1] = fmaf(ee, en, jR[rj*3+cj-1]);
            }
        }
    }

    float hmL = CM - LN2_9 * fast_lg2(prod9(sL));
    float hjL = CJ - LN2_9 * fast_lg2(prod9(jL));
    float hmR = CM - LN2_9 * fast_lg2(prod9(sR));
    float hjR = CJ - LN2_9 * fast_lg2(prod9(jR));

    // ---- stores: this thread owns channels 2*sf, 2*sf+1 of batch n ----
    if (valid) {
        float* ob = out + ((size_t)(n * 4 + sf) * 2) * HW;
        int oL = (y + 1) * WW + (x0 + 1);
        ob[oL]          = hmL;
        ob[HW + oL]     = hjL;
        ob[oL + 1]      = hmR;
        ob[HW + oL + 1] = hjR;
        zero_border(ob, x0, y);
        zero_border(ob, x0 + 1, y);
    }
}

extern "C" void kernel_launch(void* const* d_in, const int* in_sizes, int n_in,
                              void* d_out, int out_size)
{
    dim3 blk(128, 1, 1);
    dim3 grd(3, 190, 4);   // 3 blocks x 32 pairs = 96 pairs (95 valid) = 190 cols
    je11_kernel<<<grd, blk>>>((const float*)d_in[0], (float*)d_out);
}

// round 13
// speedup vs baseline: 2.4659x; 2.4659x over previous
#include <cuda_runtime.h>

// (4,4,3,192,192) fp32 -> (4,4,2,192,192): per-patch KDE entropies (R=3, h=0.1).
// R12: vertical rolling-window. Each thread owns (batch, frame, column) and
// walks a 5-patch y-strip. Sliding the 3x3 window down one row reuses 15 of 36
// pair-exps (21 fresh). Pair-exps live in six small row-group arrays whose
// rotation is compile-time slot renaming under a fully unrolled strip loop.
// Joint entropy: neighbor frame's exp shuffled at accumulation (lane+1; sf=3 self).

#define WW  192
#define HW  (192 * 192)
#define STRIP 5

#define CM     (-1.9537149f)      // log9 + 1.5*ln(2*pi*0.01)  (C=3 marginal)
#define CJ     (-6.1046541f)      // log9 + 3.0*ln(2*pi*0.01)  (C=6 joint)
#define LN2_9  (0.0770163534f)    // ln(2)/9
#define PSC2   (12.0112240f)      // sqrt(100*log2(e)): exp(-50*d2)=ex2(u.u'+nt+nt')

static __device__ __forceinline__ float fast_ex2(float x)
{ float r; asm("ex2.approx.ftz.f32 %0, %1;" : "=f"(r) : "f"(x)); return r; }

static __device__ __forceinline__ float fast_lg2(float x)
{ float r; asm("lg2.approx.f32 %0, %1;" : "=f"(r) : "f"(x)); return r; }

static __device__ __forceinline__ float prod9(const float s[9])
{
    return ((s[0] * s[1]) * (s[2] * s[3])) *
           ((s[4] * s[5]) * (s[6] * s[7])) * s[8];
}

// Load one image row (3 px x 3 chan) pre-scaled, plus -0.5|u|^2 per pixel.
static __device__ __forceinline__ void load_row(const float* __restrict__ gb,
                                                int y, float r[3][3], float ntr[3])
{
    #pragma unroll
    for (int c = 0; c < 3; ++c) {
        const float* p = gb + c * HW + y * WW;
        #pragma unroll
        for (int dx = 0; dx < 3; ++dx) r[dx][c] = p[dx] * PSC2;
    }
    #pragma unroll
    for (int dx = 0; dx < 3; ++dx) {
        float t = r[dx][0] * r[dx][0];
        t = fmaf(r[dx][1], r[dx][1], t);
        t = fmaf(r[dx][2], r[dx][2], t);
        ntr[dx] = -0.5f * t;
    }
}

// 3 pair-exps within one row: pairs (0,1), (0,2), (1,2).
static __device__ __forceinline__ void grp_within(const float r[3][3],
                                                  const float ntr[3], float g[3])
{
    #pragma unroll
    for (int k = 0; k < 3; ++k) {
        const int a = (k == 2) ? 1 : 0;
        const int b = (k == 0) ? 1 : 2;
        float v = fmaf(r[a][0], r[b][0], ntr[a]);
        v = fmaf(r[a][1], r[b][1], v);
        v = fmaf(r[a][2], r[b][2], v);
        g[k] = fast_ex2(v + ntr[b]);
    }
}

// 9 pair-exps across two rows; g[i*3+j]: i = col in OLDER row ra, j = col in rb.
static __device__ __forceinline__ void grp_cross(const float ra[3][3], const float nta[3],
                                                 const float rb[3][3], const float ntb[3],
                                                 float g[9])
{
    #pragma unroll
    for (int i = 0; i < 3; ++i)
        #pragma unroll
        for (int j = 0; j < 3; ++j) {
            float v = fmaf(ra[i][0], rb[j][0], nta[i]);
            v = fmaf(ra[i][1], rb[j][1], v);
            v = fmaf(ra[i][2], rb[j][2], v);
            g[i * 3 + j] = fast_ex2(v + ntb[j]);
        }
}

// Accumulate a within-row group into window row w.
static __device__ __forceinline__ void acc_within(const float g[3], int src,
                                                  float s[9], float sj[9], int w)
{
    #pragma unroll
    for (int k = 0; k < 3; ++k) {
        const int a = (k == 2) ? 1 : 0;
        const int b = (k == 0) ? 1 : 2;
        float e  = g[k];
        float en = __shfl_sync(0xffffffffu, e, src);
        s[w * 3 + a] += e;
        s[w * 3 + b] += e;
        sj[w * 3 + a] = fmaf(e, en, sj[w * 3 + a]);
        sj[w * 3 + b] = fmaf(e, en, sj[w * 3 + b]);
    }
}

// Accumulate a cross group (older row = window row wa, younger = wb).
static __device__ __forceinline__ void acc_cross(const float g[9], int src,
                                                 float s[9], float sj[9], int wa, int wb)
{
    #pragma unroll
    for (int i = 0; i < 3; ++i)
        #pragma unroll
        for (int j = 0; j < 3; ++j) {
            float e  = g[i * 3 + j];
            float en = __shfl_sync(0xffffffffu, e, src);
            s[wa * 3 + i] += e;
            s[wb * 3 + j] += e;
            sj[wa * 3 + i] = fmaf(e, en, sj[wa * 3 + i]);
            sj[wb * 3 + j] = fmaf(e, en, sj[wb * 3 + j]);
        }
}

// Border ring zeroing for one patch's two output channels (cold path).
static __device__ __forceinline__ void zero_border(float* ob, int x, int y)
{
    if (y == 0)   { ob[x + 1] = 0.0f;            ob[HW + x + 1] = 0.0f; }
    if (y == 189) { ob[191*WW + x + 1] = 0.0f;   ob[HW + 191*WW + x + 1] = 0.0f; }
    if (x == 0) {
        ob[(y + 1) * WW] = 0.0f;                 ob[HW + (y + 1) * WW] = 0.0f;
        if (y == 0)   { ob[0] = 0.0f;            ob[HW] = 0.0f; }
        if (y == 189) { ob[191*WW] = 0.0f;       ob[HW + 191*WW] = 0.0f; }
    }
    if (x == 189) {
        ob[(y + 1) * WW + 191] = 0.0f;           ob[HW + (y + 1) * WW + 191] = 0.0f;
        if (y == 0)   { ob[191] = 0.0f;          ob[HW + 191] = 0.0f; }
        if (y == 189) { ob[191*WW + 191] = 0.0f; ob[HW + 191*WW + 191] = 0.0f; }
    }
}

__global__ void __launch_bounds__(128)
je12_kernel(const float* __restrict__ in, float* __restrict__ out)
{
    int lane = threadIdx.x & 31;
    int warp = threadIdx.x >> 5;
    int sf   = lane & 3;          // frame handled by this lane
    int sub  = lane >> 2;         // patch-column slot within warp

    int x  = blockIdx.x * 32 + warp * 8 + sub;   // patch col (valid < 190)
    int y0 = blockIdx.y * STRIP;                 // strip start row (190 = 38*5)
    int n  = blockIdx.z;

    bool valid = (x < 190);
    int  xc    = valid ? x : 189;                // clamp: lockstep shuffles

    const float* gb = in + ((size_t)(n * 4 + sf) * 3) * HW + xc;
    float* ob = out + ((size_t)(n * 4 + sf) * 2) * HW;
    int src = (sf == 3) ? lane : (lane + 1);

    // Rolling state: 3 pixel rows (physical slots) + 6 pair-exp groups.
    float q[3][3][3];   // [slot][col][chan]
    float nt[3][3];     // [slot][col]
    float ew[3][3];     // within-row groups, by slot
    float ec[3][9];     // cross groups, unordered slot pair {a,b} -> id a+b-1

    load_row(gb, y0 + 0, q[0], nt[0]);
    load_row(gb, y0 + 1, q[1], nt[1]);
    load_row(gb, y0 + 2, q[2], nt[2]);
    grp_within(q[0], nt[0], ew[0]);
    grp_within(q[1], nt[1], ew[1]);
    grp_within(q[2], nt[2], ew[2]);
    grp_cross(q[0], nt[0], q[1], nt[1], ec[0]);  // {0,1}
    grp_cross(q[0], nt[0], q[2], nt[2], ec[1]);  // {0,2}
    grp_cross(q[1], nt[1], q[2], nt[2], ec[2]);  // {1,2}

    #pragma unroll
    for (int t = 0; t < STRIP; ++t) {
        const int p0 = t % 3;            // oldest window row (compile-time)
        const int p1 = (t + 1) % 3;
        const int p2 = (t + 2) % 3;      // youngest
        int y = y0 + t;

        // ---- accumulate all 36 pairs of this window ----
        float s[9], sj[9];
        #pragma unroll
        for (int i = 0; i < 9; ++i) { s[i] = 1.0f; sj[i] = 1.0f; }
        acc_within(ew[p0], src, s, sj, 0);
        acc_within(ew[p1], src, s, sj, 1);
        acc_within(ew[p2], src, s, sj, 2);
        acc_cross(ec[p0 + p1 - 1], src, s, sj, 0, 1);
        acc_cross(ec[p0 + p2 - 1], src, s, sj, 0, 2);
        acc_cross(ec[p1 + p2 - 1], src, s, sj, 1, 2);

        float hm = CM - LN2_9 * fast_lg2(prod9(s));
        float hj = CJ - LN2_9 * fast_lg2(prod9(sj));

        if (valid) {
            int o = (y + 1) * WW + (x + 1);
            ob[o]      = hm;
            ob[HW + o] = hj;
            zero_border(ob, x, y);
        }

        // ---- slide window: new row replaces the expiring slot p0 ----
        if (t < STRIP - 1) {
            load_row(gb, y + 3, q[p0], nt[p0]);
            grp_within(q[p0], nt[p0], ew[p0]);
            // orientation: older existing row first
            grp_cross(q[p1], nt[p1], q[p0], nt[p0], ec[p0 + p1 - 1]);
            grp_cross(q[p2], nt[p2], q[p0], nt[p0], ec[p0 + p2 - 1]);
        }
    }
}

extern "C" void kernel_launch(void* const* d_in, const int* in_sizes, int n_in,
                              void* d_out, int out_size)
{
    dim3 blk(128, 1, 1);
    dim3 grd(6, 38, 4);   // 6 blocks x 32 cols = 192 (190 valid); 38 strips x 5 = 190 rows
    je12_kernel<<<grd, blk>>>((const float*)d_in[0], (float*)d_out);
}

// round 14
// speedup vs baseline: 2.7560x; 1.1176x over previous
#include <cuda_runtime.h>

// (4,4,3,192,192) fp32 -> (4,4,2,192,192): per-patch KDE entropies (R=3, h=0.1).
// R14: rolling-window (R12) + group PARTIAL ROW-SUMS: each pair-exp's joint
// product (via shuffle) is computed once at generation; groups store per-pixel
// partial sums (marginal + joint) instead of raw exps. Window accumulation is
// 54 scalar adds, zero shuffles. 64-thread blocks reduce wave-tail imbalance.

#define WW  192
#define HW  (192 * 192)
#define STRIP 5

#define CM     (-1.9537149f)      // log9 + 1.5*ln(2*pi*0.01)  (C=3 marginal)
#define CJ     (-6.1046541f)      // log9 + 3.0*ln(2*pi*0.01)  (C=6 joint)
#define LN2_9  (0.0770163534f)    // ln(2)/9
#define PSC2   (12.0112240f)      // sqrt(100*log2(e)): exp(-50*d2)=ex2(u.u'+nt+nt')

static __device__ __forceinline__ float fast_ex2(float x)
{ float r; asm("ex2.approx.ftz.f32 %0, %1;" : "=f"(r) : "f"(x)); return r; }

static __device__ __forceinline__ float fast_lg2(float x)
{ float r; asm("lg2.approx.f32 %0, %1;" : "=f"(r) : "f"(x)); return r; }

static __device__ __forceinline__ float prod9(const float s[9])
{
    return ((s[0] * s[1]) * (s[2] * s[3])) *
           ((s[4] * s[5]) * (s[6] * s[7])) * s[8];
}

// Load one image row (3 px x 3 chan) pre-scaled, plus -0.5|u|^2 per pixel.
static __device__ __forceinline__ void load_row(const float* __restrict__ gb,
                                                int y, float r[3][3], float ntr[3])
{
    #pragma unroll
    for (int c = 0; c < 3; ++c) {
        const float* p = gb + c * HW + y * WW;
        #pragma unroll
        for (int dx = 0; dx < 3; ++dx) r[dx][c] = p[dx] * PSC2;
    }
    #pragma unroll
    for (int dx = 0; dx < 3; ++dx) {
        float t = r[dx][0] * r[dx][0];
        t = fmaf(r[dx][1], r[dx][1], t);
        t = fmaf(r[dx][2], r[dx][2], t);
        ntr[dx] = -0.5f * t;
    }
}

static __device__ __forceinline__ float pair_e(const float* a, float na,
                                               const float* b, float nb)
{
    float v = fmaf(a[0], b[0], na);
    v = fmaf(a[1], b[1], v);
    v = fmaf(a[2], b[2], v);
    return fast_ex2(v + nb);
}

// Within-row group for one slot: per-pixel partial sums of its 2 pair-exps.
static __device__ __forceinline__ void gen_within(const float r[3][3], const float ntr[3],
                                                  int src, float we[3], float wj[3])
{
    float e01 = pair_e(r[0], ntr[0], r[1], ntr[1]);
    float e02 = pair_e(r[0], ntr[0], r[2], ntr[2]);
    float e12 = pair_e(r[1], ntr[1], r[2], ntr[2]);
    float j01 = e01 * __shfl_sync(0xffffffffu, e01, src);
    float j02 = e02 * __shfl_sync(0xffffffffu, e02, src);
    float j12 = e12 * __shfl_sync(0xffffffffu, e12, src);
    we[0] = e01 + e02;  we[1] = e01 + e12;  we[2] = e02 + e12;
    wj[0] = j01 + j02;  wj[1] = j01 + j12;  wj[2] = j02 + j12;
}

// Cross group between slots sa (data ra) and sb (data rb): store per-pixel
// partial row-sums. A-side = lower-numbered slot's pixels, B-side = higher.
static __device__ __forceinline__ void gen_cross(
    const float ra[3][3], const float nta[3], int sa,
    const float rb[3][3], const float ntb[3], int sb,
    int src,
    float cAe[3][3], float cBe[3][3], float cAj[3][3], float cBj[3][3])
{
    const int gid = sa + sb - 1;   // {0,1}->0, {0,2}->1, {1,2}->2
    float ge[3][3], gj[3][3];
    #pragma unroll
    for (int i = 0; i < 3; ++i)
        #pragma unroll
        for (int j = 0; j < 3; ++j) {
            float e = pair_e(ra[i], nta[i], rb[j], ntb[j]);
            ge[i][j] = e;
            gj[i][j] = e * __shfl_sync(0xffffffffu, e, src);
        }
    #pragma unroll
    for (int i = 0; i < 3; ++i) {
        float ae = ge[i][0] + ge[i][1] + ge[i][2];        // ra-pixel i partial
        float be = ge[0][i] + ge[1][i] + ge[2][i];        // rb-pixel i partial
        float aj = gj[i][0] + gj[i][1] + gj[i][2];
        float bj = gj[0][i] + gj[1][i] + gj[2][i];
        if (sa < sb) {
            cAe[gid][i] = ae;  cBe[gid][i] = be;
            cAj[gid][i] = aj;  cBj[gid][i] = bj;
        } else {
            cAe[gid][i] = be;  cBe[gid][i] = ae;
            cAj[gid][i] = bj;  cBj[gid][i] = aj;
        }
    }
}

// Partial for slot s's pixels from group {s,o}.
static __device__ __forceinline__ float pick(const float A[3][3], const float B[3][3],
                                             int s, int o, int i)
{
    const int g = s + o - 1;
    return (s < o) ? A[g][i] : B[g][i];
}

// Border ring zeroing for one patch's two output channels (cold path).
static __device__ __forceinline__ void zero_border(float* ob, int x, int y)
{
    if (y == 0)   { ob[x + 1] = 0.0f;            ob[HW + x + 1] = 0.0f; }
    if (y == 189) { ob[191*WW + x + 1] = 0.0f;   ob[HW + 191*WW + x + 1] = 0.0f; }
    if (x == 0) {
        ob[(y + 1) * WW] = 0.0f;                 ob[HW + (y + 1) * WW] = 0.0f;
        if (y == 0)   { ob[0] = 0.0f;            ob[HW] = 0.0f; }
        if (y == 189) { ob[191*WW] = 0.0f;       ob[HW + 191*WW] = 0.0f; }
    }
    if (x == 189) {
        ob[(y + 1) * WW + 191] = 0.0f;           ob[HW + (y + 1) * WW + 191] = 0.0f;
        if (y == 0)   { ob[191] = 0.0f;          ob[HW + 191] = 0.0f; }
        if (y == 189) { ob[191*WW + 191] = 0.0f; ob[HW + 191*WW + 191] = 0.0f; }
    }
}

__global__ void __launch_bounds__(64)
je14_kernel(const float* __restrict__ in, float* __restrict__ out)
{
    int lane = threadIdx.x & 31;
    int warp = threadIdx.x >> 5;  // 0..1
    int sf   = lane & 3;          // frame handled by this lane
    int sub  = lane >> 2;         // patch-column slot within warp

    int x  = blockIdx.x * 16 + warp * 8 + sub;   // patch col (valid < 190)
    int y0 = blockIdx.y * STRIP;                 // strip start (190 = 38*5)
    int n  = blockIdx.z;

    bool valid = (x < 190);
    int  xc    = valid ? x : 189;                // clamp: lockstep shuffles

    const float* gb = in + ((size_t)(n * 4 + sf) * 3) * HW + xc;
    float* ob = out + ((size_t)(n * 4 + sf) * 2) * HW;
    int src = (sf == 3) ? lane : (lane + 1);     // frame 3 pairs with itself

    // Rolling state: 3 pixel rows + per-group partial row-sums.
    float q[3][3][3];   // [slot][col][chan]
    float nt[3][3];     // [slot][col]
    float we[3][3], wj[3][3];               // within-row partials per slot
    float cAe[3][3], cBe[3][3];             // cross partials, A=lower slot side
    float cAj[3][3], cBj[3][3];

    load_row(gb, y0 + 0, q[0], nt[0]);
    load_row(gb, y0 + 1, q[1], nt[1]);
    load_row(gb, y0 + 2, q[2], nt[2]);
    gen_within(q[0], nt[0], src, we[0], wj[0]);
    gen_within(q[1], nt[1], src, we[1], wj[1]);
    gen_within(q[2], nt[2], src, we[2], wj[2]);
    gen_cross(q[0], nt[0], 0, q[1], nt[1], 1, src, cAe, cBe, cAj, cBj);
    gen_cross(q[0], nt[0], 0, q[2], nt[2], 2, src, cAe, cBe, cAj, cBj);
    gen_cross(q[1], nt[1], 1, q[2], nt[2], 2, src, cAe, cBe, cAj, cBj);

    #pragma unroll
    for (int t = 0; t < STRIP; ++t) {
        const int p0 = t % 3;            // window row 0 (oldest), compile-time
        const int p1 = (t + 1) % 3;
        const int p2 = (t + 2) % 3;      // youngest
        int y = y0 + t;

        // ---- window accumulation: pure adds from stored partials ----
        float vm[9], vj[9];
        #pragma unroll
        for (int i = 0; i < 3; ++i) {
            vm[i]     = 1.0f + we[p0][i] + pick(cAe, cBe, p0, p1, i) + pick(cAe, cBe, p0, p2, i);
            vm[3 + i] = 1.0f + we[p1][i] + pick(cAe, cBe, p1, p0, i) + pick(cAe, cBe, p1, p2, i);
            vm[6 + i] = 1.0f + we[p2][i] + pick(cAe, cBe, p2, p0, i) + pick(cAe, cBe, p2, p1, i);
            vj[i]     = 1.0f + wj[p0][i] + pick(cAj, cBj, p0, p1, i) + pick(cAj, cBj, p0, p2, i);
            vj[3 + i] = 1.0f + wj[p1][i] + pick(cAj, cBj, p1, p0, i) + pick(cAj, cBj, p1, p2, i);
            vj[6 + i] = 1.0f + wj[p2][i] + pick(cAj, cBj, p2, p0, i) + pick(cAj, cBj, p2, p1, i);
        }
        float hm = CM - LN2_9 * fast_lg2(prod9(vm));
        float hj = CJ - LN2_9 * fast_lg2(prod9(vj));

        if (valid) {
            int o = (y + 1) * WW + (x + 1);
            ob[o]      = hm;
            ob[HW + o] = hj;
            zero_border(ob, x, y);
        }

        // ---- slide: new row replaces expiring slot p0 ----
        if (t < STRIP - 1) {
            load_row(gb, y + 3, q[p0], nt[p0]);
            gen_within(q[p0], nt[p0], src, we[p0], wj[p0]);
            gen_cross(q[p1], nt[p1], p1, q[p0], nt[p0], p0, src, cAe, cBe, cAj, cBj);
            gen_cross(q[p2], nt[p2], p2, q[p0], nt[p0], p0, src, cAe, cBe, cAj, cBj);
        }
    }
}

extern "C" void kernel_launch(void* const* d_in, const int* in_sizes, int n_in,
                              void* d_out, int out_size)
{
    dim3 blk(64, 1, 1);
    dim3 grd(12, 38, 4);  // 12 blocks x 16 cols = 192 (190 valid); 38 strips; 4 batches
    je14_kernel<<<grd, blk>>>((const float*)d_in[0], (float*)d_out);
}